// round 8
// baseline (speedup 1.0000x reference)
#include <cuda_runtime.h>
#include <math.h>

// ---------------- problem constants ----------------
#define B_ 256
#define T_ 36
#define S_ 96
#define D_ 1024
#define H_ 1024
#define L_ 2

static const long Y_SZ   = (long)B_*T_*D_;          // 9,437,184
static const long HID_SZ = (long)L_*B_*H_;          //   524,288
// attn region follows hidden in d_out

// ---------------- scratch layout (device global, no allocations) ------------
#define OFF_LOGITS 0L
#define OFF_XC     (OFF_LOGITS + (long)B_*S_)
#define OFF_GI0    (OFF_XC   + (long)B_*D_)
#define OFF_GH0    (OFF_GI0  + (long)B_*3*H_)
#define OFF_GI1    (OFF_GH0  + (long)B_*3*H_)
#define OFF_GH1    (OFF_GI1  + (long)B_*3*H_)
#define OFF_T1     (OFF_GH1  + (long)B_*3*H_)
#define OFF_YBUF   (OFF_T1   + (long)B_*D_)
#define N_ZERO     (OFF_YBUF + (long)B_*D_)          // everything before wenc is zeroed per step
#define OFF_WENC   N_ZERO
#define SC_TOTAL   (OFF_WENC + (long)B_*H_)

__device__ float g_scratch[SC_TOTAL];

// ---------------- zero kernel ----------------
__global__ void kzero4(float4* __restrict__ p, int n4) {
    int i = blockIdx.x * blockDim.x + threadIdx.x;
    int stride = gridDim.x * blockDim.x;
    float4 z = make_float4(0.f, 0.f, 0.f, 0.f);
    for (; i < n4; i += stride) p[i] = z;
}

// ---------------- split-K fp32 GEMM: C[m,n] += sum_k A[m,k]*W[n,k] ----------
// A is a virtual concat: k < K1 -> A1 (lda1), else A2 (lda2). M fixed = grid.y*64.
// Tile 64x64, 64 threads, 8x8 microtile, TK=16, register prefetch of next chunk.
// Atomic epilogue (C must be pre-zeroed; bias added by downstream kernels).
__device__ __forceinline__ float4 ldA4(const float* __restrict__ A1,
                                       const float* __restrict__ A2,
                                       int K1, int lda1, int lda2, int row, int k) {
    if (k < K1) return *reinterpret_cast<const float4*>(A1 + (long)row * lda1 + k);
    return *reinterpret_cast<const float4*>(A2 + (long)row * lda2 + (k - K1));
}

__global__ __launch_bounds__(64) void sgemm_atomic(
    const float* __restrict__ A1, const float* __restrict__ A2, int K1,
    int lda1, int lda2,
    const float* __restrict__ W, int ldw,
    float* __restrict__ C, int ldc,
    int N, int K, int Kslice)
{
    __shared__ float As[16][68];
    __shared__ float Bs[16][68];
    const int tid = threadIdx.x;
    const int tx = tid & 7, ty = tid >> 3;
    const int n0 = blockIdx.x * 64, m0 = blockIdx.y * 64;
    const int kstart = blockIdx.z * Kslice;
    const int kend = min(K, kstart + Kslice);
    const int nchunks = (kend - kstart) >> 4;

    const int lr  = tid >> 2;        // r = i*16 + lr
    const int lkq = (tid & 3) * 4;   // k sub-offset (float4)

    float acc[8][8];
#pragma unroll
    for (int i = 0; i < 8; i++)
#pragma unroll
        for (int j = 0; j < 8; j++) acc[i][j] = 0.f;

    float4 pa[4], pb[4];
    {
        int k0 = kstart;
#pragma unroll
        for (int i = 0; i < 4; i++) {
            int r = i * 16 + lr;
            pa[i] = ldA4(A1, A2, K1, lda1, lda2, m0 + r, k0 + lkq);
            int n = n0 + r;
            pb[i] = (n < N) ? *reinterpret_cast<const float4*>(W + (long)n * ldw + k0 + lkq)
                            : make_float4(0.f, 0.f, 0.f, 0.f);
        }
    }
    for (int c = 0; c < nchunks; c++) {
#pragma unroll
        for (int i = 0; i < 4; i++) {
            int r = i * 16 + lr;
            As[lkq + 0][r] = pa[i].x; As[lkq + 1][r] = pa[i].y;
            As[lkq + 2][r] = pa[i].z; As[lkq + 3][r] = pa[i].w;
            Bs[lkq + 0][r] = pb[i].x; Bs[lkq + 1][r] = pb[i].y;
            Bs[lkq + 2][r] = pb[i].z; Bs[lkq + 3][r] = pb[i].w;
        }
        __syncthreads();
        if (c + 1 < nchunks) {
            int k0 = kstart + (c + 1) * 16;
#pragma unroll
            for (int i = 0; i < 4; i++) {
                int r = i * 16 + lr;
                pa[i] = ldA4(A1, A2, K1, lda1, lda2, m0 + r, k0 + lkq);
                int n = n0 + r;
                pb[i] = (n < N) ? *reinterpret_cast<const float4*>(W + (long)n * ldw + k0 + lkq)
                                : make_float4(0.f, 0.f, 0.f, 0.f);
            }
        }
#pragma unroll
        for (int kk = 0; kk < 16; kk++) {
            float4 a0 = *reinterpret_cast<const float4*>(&As[kk][ty * 8]);
            float4 a1 = *reinterpret_cast<const float4*>(&As[kk][ty * 8 + 4]);
            float4 b0 = *reinterpret_cast<const float4*>(&Bs[kk][tx * 8]);
            float4 b1 = *reinterpret_cast<const float4*>(&Bs[kk][tx * 8 + 4]);
            float ar[8] = {a0.x, a0.y, a0.z, a0.w, a1.x, a1.y, a1.z, a1.w};
            float br[8] = {b0.x, b0.y, b0.z, b0.w, b1.x, b1.y, b1.z, b1.w};
#pragma unroll
            for (int i = 0; i < 8; i++)
#pragma unroll
                for (int j = 0; j < 8; j++)
                    acc[i][j] = fmaf(ar[i], br[j], acc[i][j]);
        }
        __syncthreads();
    }
    const int mb = m0 + ty * 8, nb = n0 + tx * 8;
#pragma unroll
    for (int i = 0; i < 8; i++) {
        float* crow = C + (long)(mb + i) * ldc + nb;
#pragma unroll
        for (int j = 0; j < 8; j++)
            if (nb + j < N) atomicAdd(crow + j, acc[i][j]);
    }
}

// ---------------- softmax over S=96 logits, writes attn output slice --------
__global__ void attn_softmax(const float* __restrict__ logits,
                             const float* __restrict__ bias,
                             float* __restrict__ outAttn, int t) {
    __shared__ float sv[S_];
    __shared__ float se[S_];
    int b = blockIdx.x, s = threadIdx.x;
    float v = logits[b * S_ + s] + bias[s];
    sv[s] = v;
    __syncthreads();
    float mx = -1e30f;
    for (int i = 0; i < S_; i++) mx = fmaxf(mx, sv[i]);
    float e = expf(v - mx);
    se[s] = e;
    __syncthreads();
    float sum = 0.f;
    for (int i = 0; i < S_; i++) sum += se[i];
    outAttn[((long)b * T_ + t) * S_ + s] = e / sum;
}

// ---------------- w_enc[b,:] = sum_s aw[b,s] * enc[b,s,:] -------------------
__global__ void weighted_enc(const float* __restrict__ outAttn, int t,
                             const float* __restrict__ enc,
                             float* __restrict__ wenc) {
    __shared__ float aw[S_];
    int b = blockIdx.x, tid = threadIdx.x;   // 256 threads, each owns 4 h via float4
    if (tid < S_) aw[tid] = outAttn[((long)b * T_ + t) * S_ + tid];
    __syncthreads();
    const float4* e = reinterpret_cast<const float4*>(enc + (long)b * S_ * H_);
    float4 acc = make_float4(0.f, 0.f, 0.f, 0.f);
#pragma unroll 4
    for (int s = 0; s < S_; s++) {
        float w = aw[s];
        float4 v = e[s * (H_ / 4) + tid];
        acc.x = fmaf(w, v.x, acc.x);
        acc.y = fmaf(w, v.y, acc.y);
        acc.z = fmaf(w, v.z, acc.z);
        acc.w = fmaf(w, v.w, acc.w);
    }
    reinterpret_cast<float4*>(wenc + (long)b * H_)[tid] = acc;
}

// ---------------- in-place bias (+ optional relu) ---------------------------
__global__ void bias_act(float* __restrict__ p, const float* __restrict__ b,
                         int cols, int relu) {
    long i = (long)blockIdx.x * blockDim.x + threadIdx.x;
    float v = p[i] + b[i % cols];
    if (relu) v = fmaxf(v, 0.f);
    p[i] = v;
}

// ---------------- GRU gate: h = (1-z)*n + z*h (in-place on h) --------------
__global__ void gru_gate(const float* __restrict__ gi, const float* __restrict__ gh,
                         const float* __restrict__ bi, const float* __restrict__ bh,
                         float* __restrict__ h) {
    int idx = blockIdx.x * blockDim.x + threadIdx.x;   // B*H
    int b = idx >> 10, j = idx & 1023;
    long base = (long)b * 3 * H_;
    float ir  = gi[base + j]          + bi[j];
    float iz  = gi[base + H_ + j]     + bi[H_ + j];
    float in_ = gi[base + 2 * H_ + j] + bi[2 * H_ + j];
    float hr  = gh[base + j]          + bh[j];
    float hz  = gh[base + H_ + j]     + bh[H_ + j];
    float hn  = gh[base + 2 * H_ + j] + bh[2 * H_ + j];
    float r = 1.f / (1.f + expf(-(ir + hr)));
    float z = 1.f / (1.f + expf(-(iz + hz)));
    float n = tanhf(in_ + r * hn);
    h[idx] = (1.f - z) * n + z * h[idx];
}

// ---------------- y slice writeback (+ out2 bias) ---------------------------
__global__ void copy_y(const float* __restrict__ ybuf, const float* __restrict__ b2,
                       float* __restrict__ outy, int t) {
    int idx = blockIdx.x * blockDim.x + threadIdx.x;   // B*D
    int b = idx >> 10, d = idx & 1023;
    outy[((long)b * T_ + t) * D_ + d] = ybuf[idx] + b2[d];
}

// ---------------- host driver ----------------
extern "C" void kernel_launch(void* const* d_in, const int* in_sizes, int n_in,
                              void* d_out, int out_size) {
    const float* target = (const float*)d_in[0];   // (B,T,D)
    const float* hidden0= (const float*)d_in[1];   // (L,B,H)
    const float* enc    = (const float*)d_in[2];   // (B,S,H)
    const float* attn_W = (const float*)d_in[3];   // (S, D+H)
    const float* attn_b = (const float*)d_in[4];
    const float* comb_W = (const float*)d_in[5];   // (D, D+H)
    const float* comb_b = (const float*)d_in[6];
    const float* W_ih   = (const float*)d_in[7];   // (L,3H,D)
    const float* W_hh   = (const float*)d_in[8];   // (L,3H,H)
    const float* b_ih   = (const float*)d_in[9];   // (L,3H)
    const float* b_hh   = (const float*)d_in[10];
    const float* out1_W = (const float*)d_in[11];  // (D,H)
    const float* out1_b = (const float*)d_in[12];
    const float* out2_W = (const float*)d_in[13];  // (D,D)
    const float* out2_b = (const float*)d_in[14];

    float* out     = (float*)d_out;
    float* outY    = out;                   // (B,T,D)
    float* hid     = out + Y_SZ;            // (L,B,H) — live recurrent state
    float* outAttn = out + Y_SZ + HID_SZ;   // (B,T,S)

    float* sc = nullptr;
    cudaGetSymbolAddress((void**)&sc, g_scratch);
    float* logits = sc + OFF_LOGITS;
    float* xc     = sc + OFF_XC;
    float* gi0    = sc + OFF_GI0;
    float* gh0    = sc + OFF_GH0;
    float* gi1    = sc + OFF_GI1;
    float* gh1    = sc + OFF_GH1;
    float* t1     = sc + OFF_T1;
    float* ybuf   = sc + OFF_YBUF;
    float* wenc   = sc + OFF_WENC;

    float* h0 = hid;
    float* h1 = hid + (long)B_ * H_;

    // initialize recurrent state from input hidden
    cudaMemcpyAsync(hid, hidden0, HID_SZ * sizeof(float),
                    cudaMemcpyDeviceToDevice, 0);

    for (int t = 0; t < T_; t++) {
        // zero all atomic-accumulated scratch for this step (~3.2 MB)
        kzero4<<<1024, 256>>>((float4*)sc, (int)(N_ZERO / 4));

        const float* x = target + (long)t * D_;   // row b at stride T*D

        // 1) attention logits: [x | h1] @ attn_W^T   (M=256, N=96, K=2048, splitK=16)
        {
            dim3 g((S_ + 63) / 64, B_ / 64, 16);
            sgemm_atomic<<<g, 64>>>(x, h1, D_, T_ * D_, H_,
                                    attn_W, D_ + H_, logits, S_, S_, D_ + H_, 128);
        }
        attn_softmax<<<B_, S_>>>(logits, attn_b, outAttn, t);
        weighted_enc<<<B_, H_ / 4>>>(outAttn, t, enc, wenc);

        // 2) combine: relu([x | w_enc] @ comb_W^T + b)   (N=1024, K=2048, splitK=4)
        {
            dim3 g(D_ / 64, B_ / 64, 4);
            sgemm_atomic<<<g, 64>>>(x, wenc, D_, T_ * D_, H_,
                                    comb_W, D_ + H_, xc, D_, D_, D_ + H_, 512);
        }
        bias_act<<<B_ * D_ / 256, 256>>>(xc, comb_b, D_, 1);

        // 3) GRU layer 0   (N=3072, K=1024, splitK=2)
        {
            dim3 g(3 * H_ / 64, B_ / 64, 2);
            sgemm_atomic<<<g, 64>>>(xc, xc, D_, D_, D_, W_ih, D_, gi0, 3 * H_,
                                    3 * H_, D_, 512);
            sgemm_atomic<<<g, 64>>>(h0, h0, H_, H_, H_, W_hh, H_, gh0, 3 * H_,
                                    3 * H_, H_, 512);
        }
        gru_gate<<<B_ * H_ / 256, 256>>>(gi0, gh0, b_ih, b_hh, h0);

        // 4) GRU layer 1
        {
            dim3 g(3 * H_ / 64, B_ / 64, 2);
            sgemm_atomic<<<g, 64>>>(h0, h0, H_, H_, H_, W_ih + (long)3 * H_ * D_,
                                    D_, gi1, 3 * H_, 3 * H_, D_, 512);
            sgemm_atomic<<<g, 64>>>(h1, h1, H_, H_, H_, W_hh + (long)3 * H_ * H_,
                                    H_, gh1, 3 * H_, 3 * H_, H_, 512);
        }
        gru_gate<<<B_ * H_ / 256, 256>>>(gi1, gh1, b_ih + 3 * H_, b_hh + 3 * H_, h1);

        // 5) output head: y = (h1 @ out1_W^T + b1) @ out2_W^T + b2
        {
            dim3 g(D_ / 64, B_ / 64, 4);
            sgemm_atomic<<<g, 64>>>(h1, h1, H_, H_, H_, out1_W, H_, t1, D_,
                                    D_, H_, 256);
        }
        bias_act<<<B_ * D_ / 256, 256>>>(t1, out1_b, D_, 0);
        {
            dim3 g(D_ / 64, B_ / 64, 4);
            sgemm_atomic<<<g, 64>>>(t1, t1, D_, D_, D_, out2_W, D_, ybuf, D_,
                                    D_, D_, 256);
        }
        copy_y<<<B_ * D_ / 256, 256>>>(ybuf, out2_b, outY, t);
    }
}

// round 9
// speedup vs baseline: 1.1397x; 1.1397x over previous
#include <cuda_runtime.h>
#include <math.h>

// ---------------- problem constants ----------------
#define B_ 256
#define T_ 36
#define S_ 96
#define D_ 1024
#define H_ 1024
#define L_ 2

static const long Y_SZ   = (long)B_*T_*D_;
static const long HID_SZ = (long)L_*B_*H_;

// ---------------- scratch layout (device global, no allocations) ------------
#define OFF_LOGITS 0L
#define OFF_XC     (OFF_LOGITS + (long)B_*S_)
#define OFF_GI0    (OFF_XC   + (long)B_*D_)
#define OFF_GH0    (OFF_GI0  + (long)B_*3*H_)
#define OFF_GI1    (OFF_GH0  + (long)B_*3*H_)
#define OFF_GH1    (OFF_GI1  + (long)B_*3*H_)
#define OFF_T1     (OFF_GH1  + (long)B_*3*H_)
#define OFF_YBUF   (OFF_T1   + (long)B_*D_)
#define N_ZERO     (OFF_YBUF + (long)B_*D_)      // everything before wenc zeroed per step
#define OFF_WENC   N_ZERO
#define SC_TOTAL   (OFF_WENC + (long)B_*H_)

__device__ float g_scratch[SC_TOTAL];

// ---------------- zero kernel ----------------
__global__ void kzero4(float4* __restrict__ p, int n4) {
    int i = blockIdx.x * blockDim.x + threadIdx.x;
    int stride = gridDim.x * blockDim.x;
    float4 z = make_float4(0.f, 0.f, 0.f, 0.f);
    for (; i < n4; i += stride) p[i] = z;
}

// ---------------- dual-problem split-K fp32 GEMM ---------------------------
// C[m,n] += sum_k f(A[m,k]) * W[n,k]; A is a virtual concat (k<K1 -> A1 else A2).
// amode: 0 = identity, 1 = relu(a + abias[k]), 2 = a + abias[k].
// blockIdx.z < s0.zcount selects set 0, else set 1 (z-local = z - s0.zcount).
// 64x64 tile, 64 threads, 8x8 microtile, TK=16, register prefetch, atomic epilogue.
struct GemmSet {
    const float* A1; const float* A2; const float* W; float* C; const float* abias;
    int K1, lda1, lda2, ldw, ldc, N, K, Kslice, amode, zcount;
};

__device__ __forceinline__ float4 ldA4t(const GemmSet& g, int row, int k) {
    float4 v;
    if (k < g.K1) v = *reinterpret_cast<const float4*>(g.A1 + (long)row * g.lda1 + k);
    else          v = *reinterpret_cast<const float4*>(g.A2 + (long)row * g.lda2 + (k - g.K1));
    if (g.amode) {
        float4 b = *reinterpret_cast<const float4*>(g.abias + k);
        v.x += b.x; v.y += b.y; v.z += b.z; v.w += b.w;
        if (g.amode == 1) {
            v.x = fmaxf(v.x, 0.f); v.y = fmaxf(v.y, 0.f);
            v.z = fmaxf(v.z, 0.f); v.w = fmaxf(v.w, 0.f);
        }
    }
    return v;
}

__global__ __launch_bounds__(64) void sgemm_dual(GemmSet s0, GemmSet s1) {
    const int zg = blockIdx.z;
    const GemmSet& g = (zg < s0.zcount) ? s0 : s1;
    const int zl = (zg < s0.zcount) ? zg : zg - s0.zcount;

    const int n0 = blockIdx.x * 64, m0 = blockIdx.y * 64;
    if (n0 >= g.N) return;

    __shared__ float As[16][68];
    __shared__ float Bs[16][68];
    const int tid = threadIdx.x;
    const int tx = tid & 7, ty = tid >> 3;
    const int kstart = zl * g.Kslice;
    const int kend = min(g.K, kstart + g.Kslice);
    const int nchunks = (kend - kstart) >> 4;

    const int lr  = tid >> 2;        // row within 16-row group
    const int lkq = (tid & 3) * 4;   // k sub-offset (float4)

    float acc[8][8];
#pragma unroll
    for (int i = 0; i < 8; i++)
#pragma unroll
        for (int j = 0; j < 8; j++) acc[i][j] = 0.f;

    float4 pa[4], pb[4];
    {
        int k0 = kstart;
#pragma unroll
        for (int i = 0; i < 4; i++) {
            int r = i * 16 + lr;
            pa[i] = ldA4t(g, m0 + r, k0 + lkq);
            int n = n0 + r;
            pb[i] = (n < g.N) ? *reinterpret_cast<const float4*>(g.W + (long)n * g.ldw + k0 + lkq)
                              : make_float4(0.f, 0.f, 0.f, 0.f);
        }
    }
    for (int c = 0; c < nchunks; c++) {
#pragma unroll
        for (int i = 0; i < 4; i++) {
            int r = i * 16 + lr;
            As[lkq + 0][r] = pa[i].x; As[lkq + 1][r] = pa[i].y;
            As[lkq + 2][r] = pa[i].z; As[lkq + 3][r] = pa[i].w;
            Bs[lkq + 0][r] = pb[i].x; Bs[lkq + 1][r] = pb[i].y;
            Bs[lkq + 2][r] = pb[i].z; Bs[lkq + 3][r] = pb[i].w;
        }
        __syncthreads();
        if (c + 1 < nchunks) {
            int k0 = kstart + (c + 1) * 16;
#pragma unroll
            for (int i = 0; i < 4; i++) {
                int r = i * 16 + lr;
                pa[i] = ldA4t(g, m0 + r, k0 + lkq);
                int n = n0 + r;
                pb[i] = (n < g.N) ? *reinterpret_cast<const float4*>(g.W + (long)n * g.ldw + k0 + lkq)
                                  : make_float4(0.f, 0.f, 0.f, 0.f);
            }
        }
#pragma unroll
        for (int kk = 0; kk < 16; kk++) {
            float4 a0 = *reinterpret_cast<const float4*>(&As[kk][ty * 8]);
            float4 a1 = *reinterpret_cast<const float4*>(&As[kk][ty * 8 + 4]);
            float4 b0 = *reinterpret_cast<const float4*>(&Bs[kk][tx * 8]);
            float4 b1 = *reinterpret_cast<const float4*>(&Bs[kk][tx * 8 + 4]);
            float ar[8] = {a0.x, a0.y, a0.z, a0.w, a1.x, a1.y, a1.z, a1.w};
            float br[8] = {b0.x, b0.y, b0.z, b0.w, b1.x, b1.y, b1.z, b1.w};
#pragma unroll
            for (int i = 0; i < 8; i++)
#pragma unroll
                for (int j = 0; j < 8; j++)
                    acc[i][j] = fmaf(ar[i], br[j], acc[i][j]);
        }
        __syncthreads();
    }
    const int mb = m0 + ty * 8, nb = n0 + tx * 8;
#pragma unroll
    for (int i = 0; i < 8; i++) {
        float* crow = g.C + (long)(mb + i) * g.ldc + nb;
#pragma unroll
        for (int j = 0; j < 8; j++)
            if (nb + j < g.N) atomicAdd(crow + j, acc[i][j]);
    }
}

// ---------------- fused softmax + weighted enc ------------------------------
// grid (2, B), 128 threads. Each block: softmax over the b-row of logits (+bias),
// writes attn output slice (chunk 0 only), then accumulates its 512-float chunk
// of w_enc[b,:] = sum_s aw[b,s] * enc[b,s,:].
__global__ void softmax_wenc(const float* __restrict__ logits,
                             const float* __restrict__ bias,
                             float* __restrict__ outAttn, int t,
                             const float* __restrict__ enc,
                             float* __restrict__ wenc) {
    __shared__ float sv[S_];
    __shared__ float se[S_];
    const int b = blockIdx.y, c = blockIdx.x, tid = threadIdx.x;
    if (tid < S_) sv[tid] = logits[b * S_ + tid] + bias[tid];
    __syncthreads();
    float mx = -1e30f;
    for (int i = 0; i < S_; i++) mx = fmaxf(mx, sv[i]);
    if (tid < S_) se[tid] = expf(sv[tid] - mx);
    __syncthreads();
    float sum = 0.f;
    for (int i = 0; i < S_; i++) sum += se[i];
    const float inv = 1.f / sum;
    if (c == 0 && tid < S_)
        outAttn[((long)b * T_ + t) * S_ + tid] = se[tid] * inv;

    const float4* e = reinterpret_cast<const float4*>(enc + (long)b * S_ * H_) + c * 128 + tid;
    float4 acc = make_float4(0.f, 0.f, 0.f, 0.f);
#pragma unroll 4
    for (int s = 0; s < S_; s++) {
        float w = se[s] * inv;
        float4 v = e[(long)s * (H_ / 4)];
        acc.x = fmaf(w, v.x, acc.x);
        acc.y = fmaf(w, v.y, acc.y);
        acc.z = fmaf(w, v.z, acc.z);
        acc.w = fmaf(w, v.w, acc.w);
    }
    reinterpret_cast<float4*>(wenc + (long)b * H_)[c * 128 + tid] = acc;
}

// ---------------- GRU gate: h = (1-z)*n + z*h (in-place on h) ---------------
__global__ void gru_gate(const float* __restrict__ gi, const float* __restrict__ gh,
                         const float* __restrict__ bi, const float* __restrict__ bh,
                         float* __restrict__ h) {
    int idx = blockIdx.x * blockDim.x + threadIdx.x;   // B*H
    int b = idx >> 10, j = idx & 1023;
    long base = (long)b * 3 * H_;
    float ir  = gi[base + j]          + bi[j];
    float iz  = gi[base + H_ + j]     + bi[H_ + j];
    float in_ = gi[base + 2 * H_ + j] + bi[2 * H_ + j];
    float hr  = gh[base + j]          + bh[j];
    float hz  = gh[base + H_ + j]     + bh[H_ + j];
    float hn  = gh[base + 2 * H_ + j] + bh[2 * H_ + j];
    float r = 1.f / (1.f + expf(-(ir + hr)));
    float z = 1.f / (1.f + expf(-(iz + hz)));
    float n = tanhf(in_ + r * hn);
    h[idx] = (1.f - z) * n + z * h[idx];
}

// ---------------- y slice writeback (+ out2 bias) ---------------------------
__global__ void copy_y(const float* __restrict__ ybuf, const float* __restrict__ b2,
                       float* __restrict__ outy, int t) {
    int idx = blockIdx.x * blockDim.x + threadIdx.x;   // B*D
    int b = idx >> 10, d = idx & 1023;
    outy[((long)b * T_ + t) * D_ + d] = ybuf[idx] + b2[d];
}

// ---------------- host driver ----------------
static inline GemmSet mkset(const float* A1, const float* A2, int K1, int lda1, int lda2,
                            const float* W, int ldw, float* C, int ldc,
                            int N, int K, int Kslice,
                            const float* abias, int amode, int zc) {
    GemmSet s;
    s.A1 = A1; s.A2 = A2; s.W = W; s.C = C; s.abias = abias;
    s.K1 = K1; s.lda1 = lda1; s.lda2 = lda2; s.ldw = ldw; s.ldc = ldc;
    s.N = N; s.K = K; s.Kslice = Kslice; s.amode = amode; s.zcount = zc;
    return s;
}

extern "C" void kernel_launch(void* const* d_in, const int* in_sizes, int n_in,
                              void* d_out, int out_size) {
    const float* target = (const float*)d_in[0];   // (B,T,D)
    const float* hidden0= (const float*)d_in[1];   // (L,B,H)
    const float* enc    = (const float*)d_in[2];   // (B,S,H)
    const float* attn_W = (const float*)d_in[3];   // (S, D+H)
    const float* attn_b = (const float*)d_in[4];
    const float* comb_W = (const float*)d_in[5];   // (D, D+H)
    const float* comb_b = (const float*)d_in[6];
    const float* W_ih   = (const float*)d_in[7];   // (L,3H,D)
    const float* W_hh   = (const float*)d_in[8];   // (L,3H,H)
    const float* b_ih   = (const float*)d_in[9];   // (L,3H)
    const float* b_hh   = (const float*)d_in[10];
    const float* out1_W = (const float*)d_in[11];  // (D,H)
    const float* out1_b = (const float*)d_in[12];
    const float* out2_W = (const float*)d_in[13];  // (D,D)
    const float* out2_b = (const float*)d_in[14];

    float* out     = (float*)d_out;
    float* outY    = out;                   // (B,T,D)
    float* hid     = out + Y_SZ;            // (L,B,H) — live recurrent state
    float* outAttn = out + Y_SZ + HID_SZ;   // (B,T,S)

    float* sc = nullptr;
    cudaGetSymbolAddress((void**)&sc, g_scratch);
    float* logits = sc + OFF_LOGITS;
    float* xc     = sc + OFF_XC;
    float* gi0    = sc + OFF_GI0;
    float* gh0    = sc + OFF_GH0;
    float* gi1    = sc + OFF_GI1;
    float* gh1    = sc + OFF_GH1;
    float* t1     = sc + OFF_T1;
    float* ybuf   = sc + OFF_YBUF;
    float* wenc   = sc + OFF_WENC;

    float* h0 = hid;
    float* h1 = hid + (long)B_ * H_;

    cudaMemcpyAsync(hid, hidden0, HID_SZ * sizeof(float),
                    cudaMemcpyDeviceToDevice, 0);

    auto xptr = [&](int t) { return target + (long)t * D_; };   // row stride T*D

    auto set_attn = [&](int t) {
        return mkset(xptr(t), h1, D_, T_ * D_, H_, attn_W, D_ + H_,
                     logits, S_, S_, D_ + H_, 256, nullptr, 0, 8);
    };
    auto set_comb = [&](int t) {
        return mkset(xptr(t), wenc, D_, T_ * D_, H_, comb_W, D_ + H_,
                     xc, D_, D_, D_ + H_, 256, nullptr, 0, 8);
    };
    // GRU layer 0: gi reads xc with fused relu(x + comb_b); gh reads h0
    auto set_gi0 = [&]() {
        return mkset(xc, xc, D_, D_, D_, W_ih, D_, gi0, 3 * H_,
                     3 * H_, D_, 256, comb_b, 1, 4);
    };
    auto set_gh0 = [&]() {
        return mkset(h0, h0, H_, H_, H_, W_hh, H_, gh0, 3 * H_,
                     3 * H_, H_, 256, nullptr, 0, 4);
    };
    auto set_gi1 = [&]() {
        return mkset(h0, h0, H_, H_, H_, W_ih + (long)3 * H_ * D_, D_,
                     gi1, 3 * H_, 3 * H_, D_, 256, nullptr, 0, 4);
    };
    auto set_gh1 = [&]() {
        return mkset(h1, h1, H_, H_, H_, W_hh + (long)3 * H_ * H_, H_,
                     gh1, 3 * H_, 3 * H_, H_, 256, nullptr, 0, 4);
    };
    auto set_out1 = [&]() {
        return mkset(h1, h1, H_, H_, H_, out1_W, H_, t1, D_,
                     D_, H_, 256, nullptr, 0, 4);
    };
    // out2 reads t1 with fused (+ out1_b)
    auto set_out2 = [&]() {
        return mkset(t1, t1, D_, D_, D_, out2_W, D_, ybuf, D_,
                     D_, D_, 256, out1_b, 2, 4);
    };

    auto launch1 = [&](const GemmSet& s) {
        dim3 g((s.N + 63) / 64, B_ / 64, s.zcount);
        GemmSet dummy = s; dummy.zcount = 0;
        sgemm_dual<<<g, 64>>>(s, dummy);
    };
    auto launch2 = [&](const GemmSet& a, const GemmSet& b) {
        int nx = max((a.N + 63) / 64, (b.N + 63) / 64);
        dim3 g(nx, B_ / 64, a.zcount + b.zcount);
        sgemm_dual<<<g, 64>>>(a, b);
    };
    auto zero = [&]() { kzero4<<<1024, 256>>>((float4*)sc, (int)(N_ZERO / 4)); };
    auto do_swenc = [&](int t) {
        softmax_wenc<<<dim3(2, B_), 128>>>(logits, attn_b, outAttn, t, enc, wenc);
    };
    auto do_gru = [&](int t) {
        launch2(set_gi0(), set_gh0());
        gru_gate<<<B_ * H_ / 256, 256>>>(gi0, gh0, b_ih, b_hh, h0);
        launch2(set_gi1(), set_gh1());
        gru_gate<<<B_ * H_ / 256, 256>>>(gi1, gh1, b_ih + 3 * H_, b_hh + 3 * H_, h1);
    };

    // ---- software-pipelined schedule: out-head(t) merged with attn/comb(t+1) ----
    // prologue: attention + combine + GRU for step 0
    zero();
    launch1(set_attn(0));
    do_swenc(0);
    launch1(set_comb(0));
    do_gru(0);

    for (int t = 0; t < T_ - 1; t++) {
        zero();                                   // clears t1/ybuf (step t) + logits/xc/gi/gh (t+1)
        launch2(set_out1(), set_attn(t + 1));     // both read h1 (post step t)
        do_swenc(t + 1);
        launch2(set_out2(), set_comb(t + 1));
        copy_y<<<B_ * D_ / 256, 256>>>(ybuf, out2_b, outY, t);
        do_gru(t + 1);
    }

    // epilogue: output head for final step
    zero();
    launch1(set_out1());
    launch1(set_out2());
    copy_y<<<B_ * D_ / 256, 256>>>(ybuf, out2_b, outY, T_ - 1);
}

// round 10
// speedup vs baseline: 1.8085x; 1.5868x over previous
#include <cuda_runtime.h>
#include <cuda_bf16.h>
#include <math.h>

// ---------------- problem constants ----------------
#define B_ 256
#define T_ 36
#define S_ 96
#define D_ 1024
#define H_ 1024
#define L_ 2

static const long Y_SZ   = (long)B_*T_*D_;
static const long HID_SZ = (long)L_*B_*H_;

// ---------------- fp32 scratch layout (device global) -----------------------
#define OFF_LOGITS 0L
#define OFF_XC     (OFF_LOGITS + (long)B_*S_)
#define OFF_GI0    (OFF_XC   + (long)B_*D_)
#define OFF_GH0    (OFF_GI0  + (long)B_*3*H_)
#define OFF_GI1    (OFF_GH0  + (long)B_*3*H_)
#define OFF_GH1    (OFF_GI1  + (long)B_*3*H_)
#define OFF_T1     (OFF_GH1  + (long)B_*3*H_)
#define OFF_YBUF   (OFF_T1   + (long)B_*D_)
#define N_ZERO     (OFF_YBUF + (long)B_*D_)      // everything before wenc zeroed per step
#define OFF_WENC   N_ZERO
#define SC_TOTAL   (OFF_WENC + (long)B_*H_)

__device__ float g_scratch[SC_TOTAL];

// ---------------- bf16 weight buffers (hi/lo split) -------------------------
#define NW_ATTN (96L*2048L)
#define NW_COMB (1024L*2048L)
#define NW_IH   (2L*3072L*1024L)
#define NW_HH   (2L*3072L*1024L)
#define NW_O1   (1024L*1024L)
#define NW_O2   (1024L*1024L)
#define OW_ATTN 0L
#define OW_COMB (OW_ATTN + NW_ATTN)
#define OW_IH   (OW_COMB + NW_COMB)
#define OW_HH   (OW_IH   + NW_IH)
#define OW_O1   (OW_HH   + NW_HH)
#define OW_O2   (OW_O1   + NW_O1)
#define TOTW    (OW_O2   + NW_O2)

__device__ __nv_bfloat16 g_whi[TOTW];
__device__ __nv_bfloat16 g_wlo[TOTW];

// ---------------- weight split conversion ----------------
__global__ void wconv(const float* __restrict__ s, __nv_bfloat16* __restrict__ hi,
                      __nv_bfloat16* __restrict__ lo, int n) {
    int i = blockIdx.x * 256 + threadIdx.x;
    if (i >= n) return;
    float v = s[i];
    __nv_bfloat16 h = __float2bfloat16(v);
    hi[i] = h;
    lo[i] = __float2bfloat16(v - __bfloat162float(h));
}

// ---------------- zero kernel ----------------
__global__ void kzero4(float4* __restrict__ p, int n4) {
    int i = blockIdx.x * blockDim.x + threadIdx.x;
    int stride = gridDim.x * blockDim.x;
    float4 z = make_float4(0.f, 0.f, 0.f, 0.f);
    for (; i < n4; i += stride) p[i] = z;
}

// ---------------- dual-problem split-K bf16-split tensor GEMM ---------------
// C[m,n] += sum_k f(A[m,k]) * W[n,k], computed as
//   hiA*hiW + hiA*loW + loA*hiW  (all fp32-accumulated via mma.m16n8k16.bf16)
// A: fp32 virtual concat (k<K1 -> A1 else A2), split to bf16 hi/lo on the fly.
// amode: 0 = identity, 1 = relu(a+abias[k]), 2 = a+abias[k] (applied pre-split).
// W: preconverted bf16 hi/lo, row-major (n, k).
// blockIdx.z < s0.zcount -> set 0 else set 1. Atomic epilogue (C pre-zeroed).
struct GemmSet {
    const float* A1; const float* A2;
    const __nv_bfloat16* Whi; const __nv_bfloat16* Wlo;
    float* C; const float* abias;
    int K1, lda1, lda2, ldw, ldc, N, K, Kslice, amode, zcount;
};

__device__ __forceinline__ float4 ldA4t(const GemmSet& g, int row, int k) {
    float4 v;
    if (k < g.K1) v = *reinterpret_cast<const float4*>(g.A1 + (long)row * g.lda1 + k);
    else          v = *reinterpret_cast<const float4*>(g.A2 + (long)row * g.lda2 + (k - g.K1));
    if (g.amode) {
        float4 b = *reinterpret_cast<const float4*>(g.abias + k);
        v.x += b.x; v.y += b.y; v.z += b.z; v.w += b.w;
        if (g.amode == 1) {
            v.x = fmaxf(v.x, 0.f); v.y = fmaxf(v.y, 0.f);
            v.z = fmaxf(v.z, 0.f); v.w = fmaxf(v.w, 0.f);
        }
    }
    return v;
}

__device__ __forceinline__ void split2(float a, float b, unsigned& h, unsigned& l) {
    __nv_bfloat16 ha = __float2bfloat16(a), hb = __float2bfloat16(b);
    __nv_bfloat16 la = __float2bfloat16(a - __bfloat162float(ha));
    __nv_bfloat16 lb = __float2bfloat16(b - __bfloat162float(hb));
    h = ((unsigned)__bfloat16_as_ushort(hb) << 16) | (unsigned)__bfloat16_as_ushort(ha);
    l = ((unsigned)__bfloat16_as_ushort(lb) << 16) | (unsigned)__bfloat16_as_ushort(la);
}

__device__ __forceinline__ void mma16816(float* c, const unsigned* a, const unsigned* b) {
    asm volatile(
        "mma.sync.aligned.m16n8k16.row.col.f32.bf16.bf16.f32 "
        "{%0,%1,%2,%3}, {%4,%5,%6,%7}, {%8,%9}, {%0,%1,%2,%3};\n"
        : "+f"(c[0]), "+f"(c[1]), "+f"(c[2]), "+f"(c[3])
        : "r"(a[0]), "r"(a[1]), "r"(a[2]), "r"(a[3]), "r"(b[0]), "r"(b[1]));
}

__device__ __forceinline__ void pfetchA(const GemmSet& g, int m0, int k0,
                                        int r, int half, float4* pa) {
#pragma unroll
    for (int c = 0; c < 4; c++)
        pa[c] = ldA4t(g, m0 + r, k0 + half * 16 + 4 * c);
}

__device__ __forceinline__ void pfetchW(const GemmSet& g, int n0, int k0,
                                        int r, int half, float4* pw) {
    int n = n0 + r;
    if (n < g.N) {
        const __nv_bfloat16* ph = g.Whi + (long)n * g.ldw + k0 + half * 16;
        const __nv_bfloat16* pl = g.Wlo + (long)n * g.ldw + k0 + half * 16;
        pw[0] = *reinterpret_cast<const float4*>(ph);
        pw[1] = *reinterpret_cast<const float4*>(ph + 8);
        pw[2] = *reinterpret_cast<const float4*>(pl);
        pw[3] = *reinterpret_cast<const float4*>(pl + 8);
    } else {
        float4 z = make_float4(0.f, 0.f, 0.f, 0.f);
        pw[0] = z; pw[1] = z; pw[2] = z; pw[3] = z;
    }
}

__global__ __launch_bounds__(128) void hgemm_dual(GemmSet s0, GemmSet s1) {
    const int zg = blockIdx.z;
    const GemmSet& g = (zg < s0.zcount) ? s0 : s1;
    const int zl = (zg < s0.zcount) ? zg : zg - s0.zcount;
    const int n0 = blockIdx.x * 64, m0 = blockIdx.y * 64;
    if (n0 >= g.N) return;

    // stride 20 u32 (= 40 bf16) per row: conflict-free for fragment loads
    __shared__ unsigned sAh[64][20], sAl[64][20], sWh[64][20], sWl[64][20];

    const int tid = threadIdx.x;
    const int warp = tid >> 5, lane = tid & 31;
    const int gq = lane >> 2, tq = lane & 3;
    const int wm0 = (warp & 1) * 32, wn0 = (warp >> 1) * 32;
    const int r = tid >> 1, half = tid & 1;

    const int kstart = zl * g.Kslice;
    const int kend = min(g.K, kstart + g.Kslice);
    const int nch = (kend - kstart) >> 5;   // KC = 32

    float acc[2][4][4];
#pragma unroll
    for (int mt = 0; mt < 2; mt++)
#pragma unroll
        for (int nt = 0; nt < 4; nt++)
#pragma unroll
            for (int q = 0; q < 4; q++) acc[mt][nt][q] = 0.f;

    float4 pa[4], pw[4];
    pfetchA(g, m0, kstart, r, half, pa);
    pfetchW(g, n0, kstart, r, half, pw);

    for (int c = 0; c < nch; c++) {
        // ---- stage smem from prefetch regs (A split to hi/lo here) ----
        {
            unsigned* da  = &sAh[r][half * 8];
            unsigned* dal = &sAl[r][half * 8];
#pragma unroll
            for (int q = 0; q < 4; q++) {
                unsigned h0, h1, l0, l1;
                split2(pa[q].x, pa[q].y, h0, l0);
                split2(pa[q].z, pa[q].w, h1, l1);
                da[2 * q] = h0;  da[2 * q + 1] = h1;
                dal[2 * q] = l0; dal[2 * q + 1] = l1;
            }
            float4* dwh = reinterpret_cast<float4*>((char*)&sWh[0][0] + r * 80 + half * 32);
            float4* dwl = reinterpret_cast<float4*>((char*)&sWl[0][0] + r * 80 + half * 32);
            dwh[0] = pw[0]; dwh[1] = pw[1];
            dwl[0] = pw[2]; dwl[1] = pw[3];
        }
        __syncthreads();
        if (c + 1 < nch) {
            int k0 = kstart + 32 * (c + 1);
            pfetchA(g, m0, k0, r, half, pa);
            pfetchW(g, n0, k0, r, half, pw);
        }
        const unsigned* pAh = &sAh[0][0];
        const unsigned* pAl = &sAl[0][0];
        const unsigned* pWh = &sWh[0][0];
        const unsigned* pWl = &sWl[0][0];
#pragma unroll
        for (int kk = 0; kk < 2; kk++) {
            const int kw = kk * 8;
            unsigned ah[2][4], al[2][4], bh[4][2], bl[4][2];
#pragma unroll
            for (int mt = 0; mt < 2; mt++) {
                int base = (wm0 + mt * 16 + gq) * 20 + kw + tq;
                ah[mt][0] = pAh[base];       ah[mt][1] = pAh[base + 160];
                ah[mt][2] = pAh[base + 4];   ah[mt][3] = pAh[base + 164];
                al[mt][0] = pAl[base];       al[mt][1] = pAl[base + 160];
                al[mt][2] = pAl[base + 4];   al[mt][3] = pAl[base + 164];
            }
#pragma unroll
            for (int nt = 0; nt < 4; nt++) {
                int base = (wn0 + nt * 8 + gq) * 20 + kw + tq;
                bh[nt][0] = pWh[base]; bh[nt][1] = pWh[base + 4];
                bl[nt][0] = pWl[base]; bl[nt][1] = pWl[base + 4];
            }
#pragma unroll
            for (int mt = 0; mt < 2; mt++)
#pragma unroll
                for (int nt = 0; nt < 4; nt++) {
                    mma16816(acc[mt][nt], ah[mt], bh[nt]);
                    mma16816(acc[mt][nt], ah[mt], bl[nt]);
                    mma16816(acc[mt][nt], al[mt], bh[nt]);
                }
        }
        __syncthreads();
    }

    // ---- atomic epilogue ----
#pragma unroll
    for (int mt = 0; mt < 2; mt++) {
        int m = m0 + wm0 + mt * 16 + gq;
#pragma unroll
        for (int nt = 0; nt < 4; nt++) {
            int n = n0 + wn0 + nt * 8 + 2 * tq;
            float* c0 = g.C + (long)m * g.ldc + n;
            float* c1 = g.C + (long)(m + 8) * g.ldc + n;
            if (n < g.N)     { atomicAdd(c0,     acc[mt][nt][0]); atomicAdd(c1,     acc[mt][nt][2]); }
            if (n + 1 < g.N) { atomicAdd(c0 + 1, acc[mt][nt][1]); atomicAdd(c1 + 1, acc[mt][nt][3]); }
        }
    }
}

// ---------------- fused softmax + weighted enc ------------------------------
__global__ void softmax_wenc(const float* __restrict__ logits,
                             const float* __restrict__ bias,
                             float* __restrict__ outAttn, int t,
                             const float* __restrict__ enc,
                             float* __restrict__ wenc) {
    __shared__ float sv[S_];
    __shared__ float se[S_];
    const int b = blockIdx.y, c = blockIdx.x, tid = threadIdx.x;
    if (tid < S_) sv[tid] = logits[b * S_ + tid] + bias[tid];
    __syncthreads();
    float mx = -1e30f;
    for (int i = 0; i < S_; i++) mx = fmaxf(mx, sv[i]);
    if (tid < S_) se[tid] = expf(sv[tid] - mx);
    __syncthreads();
    float sum = 0.f;
    for (int i = 0; i < S_; i++) sum += se[i];
    const float inv = 1.f / sum;
    if (c == 0 && tid < S_)
        outAttn[((long)b * T_ + t) * S_ + tid] = se[tid] * inv;

    const float4* e = reinterpret_cast<const float4*>(enc + (long)b * S_ * H_) + c * 128 + tid;
    float4 acc = make_float4(0.f, 0.f, 0.f, 0.f);
#pragma unroll 4
    for (int s = 0; s < S_; s++) {
        float w = se[s] * inv;
        float4 v = e[(long)s * (H_ / 4)];
        acc.x = fmaf(w, v.x, acc.x);
        acc.y = fmaf(w, v.y, acc.y);
        acc.z = fmaf(w, v.z, acc.z);
        acc.w = fmaf(w, v.w, acc.w);
    }
    reinterpret_cast<float4*>(wenc + (long)b * H_)[c * 128 + tid] = acc;
}

// ---------------- GRU gate: h = (1-z)*n + z*h (in-place on h) ---------------
__global__ void gru_gate(const float* __restrict__ gi, const float* __restrict__ gh,
                         const float* __restrict__ bi, const float* __restrict__ bh,
                         float* __restrict__ h) {
    int idx = blockIdx.x * blockDim.x + threadIdx.x;   // B*H
    int b = idx >> 10, j = idx & 1023;
    long base = (long)b * 3 * H_;
    float ir  = gi[base + j]          + bi[j];
    float iz  = gi[base + H_ + j]     + bi[H_ + j];
    float in_ = gi[base + 2 * H_ + j] + bi[2 * H_ + j];
    float hr  = gh[base + j]          + bh[j];
    float hz  = gh[base + H_ + j]     + bh[H_ + j];
    float hn  = gh[base + 2 * H_ + j] + bh[2 * H_ + j];
    float r = 1.f / (1.f + expf(-(ir + hr)));
    float z = 1.f / (1.f + expf(-(iz + hz)));
    float n = tanhf(in_ + r * hn);
    h[idx] = (1.f - z) * n + z * h[idx];
}

// ---------------- y slice writeback (+ out2 bias) ---------------------------
__global__ void copy_y(const float* __restrict__ ybuf, const float* __restrict__ b2,
                       float* __restrict__ outy, int t) {
    int idx = blockIdx.x * blockDim.x + threadIdx.x;   // B*D
    int b = idx >> 10, d = idx & 1023;
    outy[((long)b * T_ + t) * D_ + d] = ybuf[idx] + b2[d];
}

// ---------------- host driver ----------------
static inline GemmSet mkset(const float* A1, const float* A2, int K1, int lda1, int lda2,
                            const __nv_bfloat16* Whi, const __nv_bfloat16* Wlo, int ldw,
                            float* C, int ldc, int N, int K, int Kslice,
                            const float* abias, int amode, int zc) {
    GemmSet s;
    s.A1 = A1; s.A2 = A2; s.Whi = Whi; s.Wlo = Wlo; s.C = C; s.abias = abias;
    s.K1 = K1; s.lda1 = lda1; s.lda2 = lda2; s.ldw = ldw; s.ldc = ldc;
    s.N = N; s.K = K; s.Kslice = Kslice; s.amode = amode; s.zcount = zc;
    return s;
}

extern "C" void kernel_launch(void* const* d_in, const int* in_sizes, int n_in,
                              void* d_out, int out_size) {
    const float* target = (const float*)d_in[0];   // (B,T,D)
    const float* hidden0= (const float*)d_in[1];   // (L,B,H)
    const float* enc    = (const float*)d_in[2];   // (B,S,H)
    const float* attn_W = (const float*)d_in[3];   // (S, D+H)
    const float* attn_b = (const float*)d_in[4];
    const float* comb_W = (const float*)d_in[5];   // (D, D+H)
    const float* comb_b = (const float*)d_in[6];
    const float* W_ih   = (const float*)d_in[7];   // (L,3H,D)
    const float* W_hh   = (const float*)d_in[8];   // (L,3H,H)
    const float* b_ih   = (const float*)d_in[9];   // (L,3H)
    const float* b_hh   = (const float*)d_in[10];
    const float* out1_W = (const float*)d_in[11];  // (D,H)
    const float* out1_b = (const float*)d_in[12];
    const float* out2_W = (const float*)d_in[13];  // (D,D)
    const float* out2_b = (const float*)d_in[14];

    float* out     = (float*)d_out;
    float* outY    = out;                   // (B,T,D)
    float* hid     = out + Y_SZ;            // (L,B,H) — live recurrent state
    float* outAttn = out + Y_SZ + HID_SZ;   // (B,T,S)

    float* sc = nullptr;
    cudaGetSymbolAddress((void**)&sc, g_scratch);
    __nv_bfloat16* whi = nullptr; __nv_bfloat16* wlo = nullptr;
    cudaGetSymbolAddress((void**)&whi, g_whi);
    cudaGetSymbolAddress((void**)&wlo, g_wlo);

    float* logits = sc + OFF_LOGITS;
    float* xc     = sc + OFF_XC;
    float* gi0    = sc + OFF_GI0;
    float* gh0    = sc + OFF_GH0;
    float* gi1    = sc + OFF_GI1;
    float* gh1    = sc + OFF_GH1;
    float* t1     = sc + OFF_T1;
    float* ybuf   = sc + OFF_YBUF;
    float* wenc   = sc + OFF_WENC;

    float* h0 = hid;
    float* h1 = hid + (long)B_ * H_;

    // weight hi/lo split (per replay; deterministic)
    {
        struct { const float* s; long off; long n; } cv[6] = {
            {attn_W, OW_ATTN, NW_ATTN}, {comb_W, OW_COMB, NW_COMB},
            {W_ih,   OW_IH,   NW_IH},   {W_hh,   OW_HH,   NW_HH},
            {out1_W, OW_O1,   NW_O1},   {out2_W, OW_O2,   NW_O2}};
        for (int i = 0; i < 6; i++)
            wconv<<<(int)((cv[i].n + 255) / 256), 256>>>(cv[i].s, whi + cv[i].off,
                                                         wlo + cv[i].off, (int)cv[i].n);
    }

    cudaMemcpyAsync(hid, hidden0, HID_SZ * sizeof(float),
                    cudaMemcpyDeviceToDevice, 0);

    auto xptr = [&](int t) { return target + (long)t * D_; };   // row stride T*D

    auto set_attn = [&](int t) {
        return mkset(xptr(t), h1, D_, T_ * D_, H_, whi + OW_ATTN, wlo + OW_ATTN, D_ + H_,
                     logits, S_, S_, D_ + H_, 256, nullptr, 0, 8);
    };
    auto set_comb = [&](int t) {
        return mkset(xptr(t), wenc, D_, T_ * D_, H_, whi + OW_COMB, wlo + OW_COMB, D_ + H_,
                     xc, D_, D_, D_ + H_, 256, nullptr, 0, 8);
    };
    auto set_gi0 = [&]() {  // reads xc with fused relu(x + comb_b)
        return mkset(xc, xc, D_, D_, D_, whi + OW_IH, wlo + OW_IH, D_,
                     gi0, 3 * H_, 3 * H_, D_, 256, comb_b, 1, 4);
    };
    auto set_gh0 = [&]() {
        return mkset(h0, h0, H_, H_, H_, whi + OW_HH, wlo + OW_HH, H_,
                     gh0, 3 * H_, 3 * H_, H_, 256, nullptr, 0, 4);
    };
    auto set_gi1 = [&]() {
        return mkset(h0, h0, H_, H_, H_, whi + OW_IH + (long)3 * H_ * D_,
                     wlo + OW_IH + (long)3 * H_ * D_, D_,
                     gi1, 3 * H_, 3 * H_, D_, 256, nullptr, 0, 4);
    };
    auto set_gh1 = [&]() {
        return mkset(h1, h1, H_, H_, H_, whi + OW_HH + (long)3 * H_ * H_,
                     wlo + OW_HH + (long)3 * H_ * H_, H_,
                     gh1, 3 * H_, 3 * H_, H_, 256, nullptr, 0, 4);
    };
    auto set_out1 = [&]() {
        return mkset(h1, h1, H_, H_, H_, whi + OW_O1, wlo + OW_O1, H_,
                     t1, D_, D_, H_, 256, nullptr, 0, 4);
    };
    auto set_out2 = [&]() {  // reads t1 with fused (+ out1_b)
        return mkset(t1, t1, D_, D_, D_, whi + OW_O2, wlo + OW_O2, D_,
                     ybuf, D_, D_, D_, 256, out1_b, 2, 4);
    };

    auto launch1 = [&](const GemmSet& s) {
        dim3 g((s.N + 63) / 64, B_ / 64, s.zcount);
        GemmSet dummy = s; dummy.zcount = 0;
        hgemm_dual<<<g, 128>>>(s, dummy);
    };
    auto launch2 = [&](const GemmSet& a, const GemmSet& b) {
        int nx = max((a.N + 63) / 64, (b.N + 63) / 64);
        dim3 g(nx, B_ / 64, a.zcount + b.zcount);
        hgemm_dual<<<g, 128>>>(a, b);
    };
    auto zero = [&]() { kzero4<<<1024, 256>>>((float4*)sc, (int)(N_ZERO / 4)); };
    auto do_swenc = [&](int t) {
        softmax_wenc<<<dim3(2, B_), 128>>>(logits, attn_b, outAttn, t, enc, wenc);
    };
    auto do_gru = [&](int t) {
        launch2(set_gi0(), set_gh0());
        gru_gate<<<B_ * H_ / 256, 256>>>(gi0, gh0, b_ih, b_hh, h0);
        launch2(set_gi1(), set_gh1());
        gru_gate<<<B_ * H_ / 256, 256>>>(gi1, gh1, b_ih + 3 * H_, b_hh + 3 * H_, h1);
    };

    // ---- software-pipelined schedule: out-head(t) merged with attn/comb(t+1) ----
    zero();
    launch1(set_attn(0));
    do_swenc(0);
    launch1(set_comb(0));
    do_gru(0);

    for (int t = 0; t < T_ - 1; t++) {
        zero();                                   // clears t1/ybuf (step t) + logits/xc/gi/gh (t+1)
        launch2(set_out1(), set_attn(t + 1));     // both read h1 (post step t)
        do_swenc(t + 1);
        launch2(set_out2(), set_comb(t + 1));
        copy_y<<<B_ * D_ / 256, 256>>>(ybuf, out2_b, outY, t);
        do_gru(t + 1);
    }

    zero();
    launch1(set_out1());
    launch1(set_out2());
    copy_y<<<B_ * D_ / 256, 256>>>(ybuf, out2_b, outY, T_ - 1);
}